// round 13
// baseline (speedup 1.0000x reference)
#include <cuda_runtime.h>
#include <cuda_fp16.h>
#include <cstdint>
#include <cstddef>

#define BB   4
#define CC   128
#define SS   32
#define OCC  128
#define EPSF 1e-8f

#define NTAP   27
#define BH_ROWS 1020                 // 3 planes x 10 w x 34 dd
#define BH_BYTES (BH_ROWS * 128)     // 130560
#define A_BYTES 16384                // 128 oc x 128B (64 ic fp16)
#define NBUF_A 6
#define A_OFF  BH_BYTES
#define CTRL_OFF (A_OFF + NBUF_A * A_BYTES)   // 228864
#define SMEM_TOTAL (CTRL_OFF + 16)
#define NTHR 512
#define NITEM 1024                   // 512 tiles x 2 ic-passes
#define GRID 148

__device__ float g_demod[BB * OCC];
__device__ unsigned g_ctr;
__device__ __align__(256) __half g_w16[NTAP * 2 * 128 * 64];
__device__ __align__(256) __half g_x16[(size_t)BB * SS * SS * SS * CC];

// ---------------- PTX helpers ----------------
__device__ __forceinline__ uint32_t smem_u32(const void* p) {
    uint32_t a;
    asm("{ .reg .u64 t; cvta.to.shared.u64 t, %1; cvt.u32.u64 %0, t; }" : "=r"(a) : "l"(p));
    return a;
}
__device__ __forceinline__ void cpasync16(uint32_t dst, const void* src, int sz) {
    asm volatile("cp.async.cg.shared.global [%0], [%1], 16, %2;"
                 :: "r"(dst), "l"(src), "r"(sz) : "memory");
}
#define CP_COMMIT() asm volatile("cp.async.commit_group;" ::: "memory")
#define CP_WAIT(n)  asm volatile("cp.async.wait_group %0;" :: "n"(n) : "memory")

__device__ __forceinline__ void ldsm4(uint32_t& r0, uint32_t& r1, uint32_t& r2,
                                      uint32_t& r3, uint32_t addr) {
    asm volatile("ldmatrix.sync.aligned.m8n8.x4.shared.b16 {%0,%1,%2,%3}, [%4];"
                 : "=r"(r0), "=r"(r1), "=r"(r2), "=r"(r3) : "r"(addr));
}
__device__ __forceinline__ void mma16816(float* c, const uint32_t* a, const uint32_t* b) {
    asm volatile(
        "mma.sync.aligned.m16n8k16.row.col.f32.f16.f16.f32 "
        "{%0,%1,%2,%3}, {%4,%5,%6,%7}, {%8,%9}, {%0,%1,%2,%3};"
        : "+f"(c[0]), "+f"(c[1]), "+f"(c[2]), "+f"(c[3])
        : "r"(a[0]), "r"(a[1]), "r"(a[2]), "r"(a[3]), "r"(b[0]), "r"(b[1]));
}
// swizzled addr of (row, colByte) in a 128B-row tile
__device__ __forceinline__ uint32_t rowaddr(uint32_t row, uint32_t colb) {
    return (row << 7) + (colb ^ ((row & 7) << 4));
}

// ---------------- prepass: zero output ----------------
__global__ __launch_bounds__(256) void zero_kernel(float4* __restrict__ out, int n4) {
    int i = blockIdx.x * 256 + threadIdx.x;
    int stride = gridDim.x * 256;
    float4 z = make_float4(0.f, 0.f, 0.f, 0.f);
    for (; i < n4; i += stride) out[i] = z;
}

// ---------------- prepass: demod (+ counter reset) ----------------
__global__ void demod_kernel(const float* __restrict__ y, const float* __restrict__ w) {
    int oc = blockIdx.x, ic = threadIdx.x;
    if (oc == 0 && ic == 0) g_ctr = GRID;
    const float* wp = w + (oc * CC + ic) * 27;
    float wsum = 0.f;
#pragma unroll
    for (int t = 0; t < 27; t++) { float v = wp[t]; wsum += v * v; }
    __shared__ float red[CC];
    for (int b = 0; b < BB; b++) {
        float yv = y[b * CC + ic];
        red[ic] = wsum * yv * yv;
        __syncthreads();
        for (int s = CC / 2; s > 0; s >>= 1) {
            if (ic < s) red[ic] += red[ic + s];
            __syncthreads();
        }
        if (ic == 0) g_demod[b * OCC + oc] = rsqrtf(red[0] + EPSF);
        __syncthreads();
    }
}

// ---------------- prepass: weight fp16, layout [tap*2+ichalf][oc][icl] ----------------
__global__ void wconv_kernel(const float* __restrict__ w) {
    int oc = blockIdx.x, ic = threadIdx.x;
    int ichalf = ic >> 6, icl = ic & 63;
#pragma unroll 1
    for (int t = 0; t < 27; t++) {
        float v = w[(oc * CC + ic) * 27 + t];
        int st = t * 2 + ichalf;
        g_w16[(st * 128 + oc) * 64 + icl] = __float2half(v);
    }
}

// ---------------- prepass: x transpose + y fold -> fp16; [b,h,w,d][ic] ----------------
__global__ __launch_bounds__(256) void xconv_kernel(const float* __restrict__ x,
                                                    const float* __restrict__ y) {
    __shared__ float ts[128][33];
    int w_ = blockIdx.x, h = blockIdx.y, b = blockIdx.z;
    int tid = threadIdx.x;
#pragma unroll
    for (int k = 0; k < 16; k++) {
        int e = tid + k * 256;
        int ic = e >> 5, d = e & 31;
        ts[ic][d] = x[((size_t)(b * CC + ic) * SS + h) * 1024 + w_ * SS + d] * y[b * CC + ic];
    }
    __syncthreads();
    size_t nb = (((size_t)(b * SS + h) * SS + w_) * SS) * CC;
#pragma unroll
    for (int k = 0; k < 16; k++) {
        int e = tid + k * 256;
        int d = e >> 7, ic = e & 127;
        g_x16[nb + (size_t)d * CC + ic] = __float2half(ts[ic][d]);
    }
}

// ---------------- B halo loader: 1020 rows, zero-filled halo ----------------
__device__ __forceinline__ void load_bhalo(uint32_t sb, int tid, int pass,
                                           int b, int h, int w0) {
#pragma unroll 1
    for (int k = 0; k < 16; k++) {
        int i = tid + k * NTHR;
        if (i < BH_ROWS * 8) {
            int r = i >> 3, c = i & 7;
            int plane = r / 340;
            int rem   = r - plane * 340;
            int lw    = rem / 34;
            int dd    = rem - lw * 34;
            int gh = h + plane - 1, gw = w0 + lw - 1, gd = dd - 1;
            bool ok = (unsigned)gh < 32u && (unsigned)gw < 32u && (unsigned)gd < 32u;
            size_t n = ok ? (((size_t)(b * SS + gh) * SS + gw) * SS + gd) : 0;
            const char* src = (const char*)g_x16 + (n * CC + pass * 64) * 2 + c * 16;
            cpasync16(sb + rowaddr((uint32_t)r, c * 16), src, ok ? 16 : 0);
        }
    }
    CP_COMMIT();
}

// ---------------- A group loader: taps 3g..3g+2 into buffer set (g&1)*3 ----------------
__device__ __forceinline__ void load_agroup(uint32_t sb, int tid, int g, int pass) {
    int bufbase = (g & 1) * 3;
#pragma unroll
    for (int i = 0; i < 3; i++) {
        int tap = g * 3 + i;
        const char* ws = (const char*)(g_w16 + (size_t)(tap * 2 + pass) * 128 * 64);
        uint32_t base = sb + A_OFF + (bufbase + i) * A_BYTES;
#pragma unroll
        for (int k = 0; k < 2; k++) {
            int idx = tid + k * NTHR;
            int row = idx >> 3, c = idx & 7;
            cpasync16(base + rowaddr((uint32_t)row, c * 16),
                      ws + (size_t)row * 128 + c * 16, 16);
        }
    }
    CP_COMMIT();
}

// ---------------- main conv: persistent implicit GEMM, split-pass items ----------------
__global__ __launch_bounds__(NTHR, 1) void conv_kernel(float* __restrict__ out) {
    extern __shared__ char smem[];
    uint32_t sb = smem_u32(smem);
    unsigned* next_item = (unsigned*)(smem + CTRL_OFF);
    int tid = threadIdx.x;
    int wid = tid >> 5, lid = tid & 31;
    int phase = wid >> 2;               // stagger kk across warps of same SMSP

    // warp grid: 4m x 4n ; warp tile 32(M) x 64(N)
    int warp_m = (wid & 3) * 32;
    int warp_n = (wid >> 2) * 64;

    // A: per-lane swizzled base offsets (within a 16KB A buffer)
    uint32_t sa[2];
#pragma unroll
    for (int mi = 0; mi < 2; mi++)
        sa[mi] = rowaddr((uint32_t)(warp_m + mi * 16 + (lid & 15)), (lid >> 4) * 16);

    // B: per-lane halo row base (n -> wl*34 + d) and col byte
    uint32_t brow[4];
    uint32_t bcol = ((lid >> 3) & 1) * 16;
#pragma unroll
    for (int nj2 = 0; nj2 < 4; nj2++) {
        int n = warp_n + nj2 * 16 + (lid & 7) + ((lid >> 4) & 1) * 8;
        brow[nj2] = (uint32_t)((n >> 5) * 34 + (n & 31));
    }

    unsigned item = blockIdx.x;
    while (item < NITEM) {
        int pass = item & 1;
        unsigned tile = item >> 1;
        int b  = tile >> 7;
        int h  = (tile >> 2) & 31;
        int w0 = (tile & 3) * 8;

        float acc[2][8][4];
#pragma unroll
        for (int mi = 0; mi < 2; mi++)
#pragma unroll
            for (int nj = 0; nj < 8; nj++)
#pragma unroll
                for (int q = 0; q < 4; q++) acc[mi][nj][q] = 0.f;

        load_bhalo(sb, tid, pass, b, h, w0);   // commit
        load_agroup(sb, tid, 0, pass);         // commit

#pragma unroll 1
        for (int g = 0; g < 9; g++) {
            CP_WAIT(0);            // group g (and bhalo at g=0) resident
            __syncthreads();       // all warps done with overwritten buffer set
            if (g < 8) load_agroup(sb, tid, g + 1, pass);  // hidden under compute

#pragma unroll
            for (int i = 0; i < 3; i++) {
                int t = g * 3 + i;
                int kh = t / 9, r9 = t - kh * 9;
                int kw = r9 / 3, kd = r9 - kw * 3;
                uint32_t tapoff = (uint32_t)(kh * 340 + kw * 34 + kd);

                uint32_t Ab = sb + A_OFF + ((g & 1) * 3 + i) * A_BYTES;
                uint32_t sbb[4];
#pragma unroll
                for (int nj2 = 0; nj2 < 4; nj2++)
                    sbb[nj2] = sb + rowaddr(brow[nj2] + tapoff, bcol);

#pragma unroll
                for (int kq = 0; kq < 4; kq++) {
                    uint32_t kx = (uint32_t)(((kq + phase) & 3) * 32);
                    uint32_t a[2][4];
#pragma unroll
                    for (int mi = 0; mi < 2; mi++)
                        ldsm4(a[mi][0], a[mi][1], a[mi][2], a[mi][3], Ab + (sa[mi] ^ kx));
                    uint32_t bf[8][2];
#pragma unroll
                    for (int nj2 = 0; nj2 < 4; nj2++)
                        ldsm4(bf[2 * nj2][0], bf[2 * nj2][1], bf[2 * nj2 + 1][0],
                              bf[2 * nj2 + 1][1], sbb[nj2] ^ kx);
#pragma unroll
                    for (int mi = 0; mi < 2; mi++)
#pragma unroll
                        for (int nj = 0; nj < 8; nj++)
                            mma16816(acc[mi][nj], a[mi], bf[nj]);
                }
            }
        }

        // ---- prefetch next item id (latency hides under epilogue) ----
        if (tid == 0) *next_item = atomicAdd(&g_ctr, 1u);

        // ---- epilogue: demod scale + atomic accumulate (2 addends/output) ----
#pragma unroll
        for (int mi = 0; mi < 2; mi++) {
#pragma unroll
            for (int rr = 0; rr < 2; rr++) {
                int oc = warp_m + mi * 16 + (lid >> 2) + rr * 8;
                float dm = g_demod[b * OCC + oc];
                float* obase = out + ((size_t)(b * OCC + oc) * SS + h) * 1024;
#pragma unroll
                for (int nj = 0; nj < 8; nj++) {
                    int n = warp_n + nj * 8 + 2 * (lid & 3);
                    int wl_ = n >> 5, d = n & 31;
                    float* p = obase + (w0 + wl_) * 32 + d;
                    atomicAdd(p,     acc[mi][nj][2 * rr + 0] * dm);
                    atomicAdd(p + 1, acc[mi][nj][2 * rr + 1] * dm);
                }
            }
        }

        __syncthreads();           // epilogue done; halo safe to overwrite; next_item visible
        item = *next_item;
    }
}

// ---------------------------------------------------------------------------
extern "C" void kernel_launch(void* const* d_in, const int* in_sizes, int n_in,
                              void* d_out, int out_size) {
    const float* x = (const float*)d_in[0];
    const float* y = (const float*)d_in[1];
    const float* w = (const float*)d_in[2];
    float* out = (float*)d_out;

    cudaFuncSetAttribute(conv_kernel, cudaFuncAttributeMaxDynamicSharedMemorySize,
                         SMEM_TOTAL);

    zero_kernel<<<4096, 256>>>((float4*)out, out_size / 4);
    demod_kernel<<<OCC, CC>>>(y, w);
    wconv_kernel<<<OCC, CC>>>(w);
    xconv_kernel<<<dim3(SS, SS, BB), 256>>>(x, y);
    conv_kernel<<<GRID, NTHR, SMEM_TOTAL>>>(out);
}

// round 14
// speedup vs baseline: 1.0262x; 1.0262x over previous
#include <cuda_runtime.h>
#include <cuda_fp16.h>
#include <cstdint>
#include <cstddef>

#define BB   4
#define CC   128
#define SS   32
#define OCC  128
#define EPSF 1e-8f

#define NTAP   27
#define BH_ROWS 612                  // 3 planes x 6 w x 34 dd
#define BH_BYTES (BH_ROWS * 128)     // 78336
#define A_BYTES 16384                // 128 oc x 128B (64 ic fp16)
#define NBUF_A 6
#define A_OFF  BH_BYTES
#define CTRL_OFF (A_OFF + NBUF_A * A_BYTES)   // 176640
#define SMEM_TOTAL (CTRL_OFF + 16)
#define NTHR 512
#define NITEM 1024                   // 4 b x 32 h x 8 w-quads
#define GRID 148

__device__ float g_demod[BB * OCC];
__device__ unsigned g_ctr;
__device__ __align__(256) __half g_w16[NTAP * 2 * 128 * 64];
__device__ __align__(256) __half g_x16[(size_t)BB * SS * SS * SS * CC];

// ---------------- PTX helpers ----------------
__device__ __forceinline__ uint32_t smem_u32(const void* p) {
    uint32_t a;
    asm("{ .reg .u64 t; cvta.to.shared.u64 t, %1; cvt.u32.u64 %0, t; }" : "=r"(a) : "l"(p));
    return a;
}
__device__ __forceinline__ void cpasync16(uint32_t dst, const void* src, int sz) {
    asm volatile("cp.async.cg.shared.global [%0], [%1], 16, %2;"
                 :: "r"(dst), "l"(src), "r"(sz) : "memory");
}
#define CP_COMMIT() asm volatile("cp.async.commit_group;" ::: "memory")
#define CP_WAIT(n)  asm volatile("cp.async.wait_group %0;" :: "n"(n) : "memory")

__device__ __forceinline__ void ldsm4(uint32_t& r0, uint32_t& r1, uint32_t& r2,
                                      uint32_t& r3, uint32_t addr) {
    asm volatile("ldmatrix.sync.aligned.m8n8.x4.shared.b16 {%0,%1,%2,%3}, [%4];"
                 : "=r"(r0), "=r"(r1), "=r"(r2), "=r"(r3) : "r"(addr));
}
__device__ __forceinline__ void mma16816(float* c, const uint32_t* a, const uint32_t* b) {
    asm volatile(
        "mma.sync.aligned.m16n8k16.row.col.f32.f16.f16.f32 "
        "{%0,%1,%2,%3}, {%4,%5,%6,%7}, {%8,%9}, {%0,%1,%2,%3};"
        : "+f"(c[0]), "+f"(c[1]), "+f"(c[2]), "+f"(c[3])
        : "r"(a[0]), "r"(a[1]), "r"(a[2]), "r"(a[3]), "r"(b[0]), "r"(b[1]));
}
// swizzled addr of (row, colByte) in a 128B-row tile
__device__ __forceinline__ uint32_t rowaddr(uint32_t row, uint32_t colb) {
    return (row << 7) + (colb ^ ((row & 7) << 4));
}

// ---------------- prepass: demod (+ counter reset) ----------------
__global__ void demod_kernel(const float* __restrict__ y, const float* __restrict__ w) {
    int oc = blockIdx.x, ic = threadIdx.x;
    if (oc == 0 && ic == 0) g_ctr = GRID;
    const float* wp = w + (oc * CC + ic) * 27;
    float wsum = 0.f;
#pragma unroll
    for (int t = 0; t < 27; t++) { float v = wp[t]; wsum += v * v; }
    __shared__ float red[CC];
    for (int b = 0; b < BB; b++) {
        float yv = y[b * CC + ic];
        red[ic] = wsum * yv * yv;
        __syncthreads();
        for (int s = CC / 2; s > 0; s >>= 1) {
            if (ic < s) red[ic] += red[ic + s];
            __syncthreads();
        }
        if (ic == 0) g_demod[b * OCC + oc] = rsqrtf(red[0] + EPSF);
        __syncthreads();
    }
}

// ---------------- prepass: weight fp16, layout [tap*2+ichalf][oc][icl] ----------------
__global__ void wconv_kernel(const float* __restrict__ w) {
    int oc = blockIdx.x, ic = threadIdx.x;
    int ichalf = ic >> 6, icl = ic & 63;
#pragma unroll 1
    for (int t = 0; t < 27; t++) {
        float v = w[(oc * CC + ic) * 27 + t];
        int st = t * 2 + ichalf;
        g_w16[(st * 128 + oc) * 64 + icl] = __float2half(v);
    }
}

// ---------------- prepass: x transpose + y fold -> fp16; [b,h,w,d][ic] ----------------
__global__ __launch_bounds__(256) void xconv_kernel(const float* __restrict__ x,
                                                    const float* __restrict__ y) {
    __shared__ float ts[128][33];
    int w_ = blockIdx.x, h = blockIdx.y, b = blockIdx.z;
    int tid = threadIdx.x;
#pragma unroll
    for (int k = 0; k < 16; k++) {
        int e = tid + k * 256;
        int ic = e >> 5, d = e & 31;
        ts[ic][d] = x[((size_t)(b * CC + ic) * SS + h) * 1024 + w_ * SS + d] * y[b * CC + ic];
    }
    __syncthreads();
    size_t nb = (((size_t)(b * SS + h) * SS + w_) * SS) * CC;
#pragma unroll
    for (int k = 0; k < 16; k++) {
        int e = tid + k * 256;
        int d = e >> 7, ic = e & 127;
        g_x16[nb + (size_t)d * CC + ic] = __float2half(ts[ic][d]);
    }
}

// ---------------- B halo loader: 612 rows, zero-filled halo ----------------
__device__ __forceinline__ void load_bhalo(uint32_t sb, int tid, int pass,
                                           int b, int h, int w0) {
#pragma unroll 1
    for (int k = 0; k < 10; k++) {
        int i = tid + k * NTHR;
        if (i < BH_ROWS * 8) {
            int r = i >> 3, c = i & 7;
            int plane = r / 204;
            int rem   = r - plane * 204;
            int lw    = rem / 34;
            int dd    = rem - lw * 34;
            int gh = h + plane - 1, gw = w0 + lw - 1, gd = dd - 1;
            bool ok = (unsigned)gh < 32u && (unsigned)gw < 32u && (unsigned)gd < 32u;
            size_t n = ok ? (((size_t)(b * SS + gh) * SS + gw) * SS + gd) : 0;
            const char* src = (const char*)g_x16 + (n * CC + pass * 64) * 2 + c * 16;
            cpasync16(sb + rowaddr((uint32_t)r, c * 16), src, ok ? 16 : 0);
        }
    }
    CP_COMMIT();
}

// ---------------- A group loader: taps 3g..3g+2 into buffer set (g&1)*3 ----------------
__device__ __forceinline__ void load_agroup(uint32_t sb, int tid, int g, int pass) {
    int bufbase = (g & 1) * 3;
#pragma unroll
    for (int i = 0; i < 3; i++) {
        int tap = g * 3 + i;
        const char* ws = (const char*)(g_w16 + (size_t)(tap * 2 + pass) * 128 * 64);
        uint32_t base = sb + A_OFF + (bufbase + i) * A_BYTES;
#pragma unroll
        for (int k = 0; k < 2; k++) {
            int idx = tid + k * NTHR;
            int row = idx >> 3, c = idx & 7;
            cpasync16(base + rowaddr((uint32_t)row, c * 16),
                      ws + (size_t)row * 128 + c * 16, 16);
        }
    }
    CP_COMMIT();
}

// ---------------- main conv: persistent implicit GEMM, N-split items ----------------
__global__ __launch_bounds__(NTHR, 1) void conv_kernel(float* __restrict__ out) {
    extern __shared__ char smem[];
    uint32_t sb = smem_u32(smem);
    unsigned* next_item = (unsigned*)(smem + CTRL_OFF);
    int tid = threadIdx.x;
    int wid = tid >> 5, lid = tid & 31;
    int phase = wid >> 2;               // stagger kk across warps of same SMSP

    // warp grid: 4m x 4n ; warp tile 32(M) x 32(N)
    int warp_m = (wid & 3) * 32;
    int warp_n = (wid >> 2) * 32;

    // A: per-lane swizzled base offsets (within a 16KB A buffer)
    uint32_t sa[2];
#pragma unroll
    for (int mi = 0; mi < 2; mi++)
        sa[mi] = rowaddr((uint32_t)(warp_m + mi * 16 + (lid & 15)), (lid >> 4) * 16);

    // B: per-lane halo row base (n -> lw*34 + d) and col byte
    uint32_t brow[2];
    uint32_t bcol = ((lid >> 3) & 1) * 16;
#pragma unroll
    for (int nj2 = 0; nj2 < 2; nj2++) {
        int n = warp_n + nj2 * 16 + (lid & 7) + ((lid >> 4) & 1) * 8;
        brow[nj2] = (uint32_t)((n >> 5) * 34 + (n & 31));
    }

    unsigned item = blockIdx.x;
    while (item < NITEM) {
        int b  = item >> 8;
        int h  = (item >> 3) & 31;
        int w0 = (item & 7) * 4;

        float acc[2][4][4];
#pragma unroll
        for (int mi = 0; mi < 2; mi++)
#pragma unroll
            for (int nj = 0; nj < 4; nj++)
#pragma unroll
                for (int q = 0; q < 4; q++) acc[mi][nj][q] = 0.f;

#pragma unroll 1
        for (int pass = 0; pass < 2; pass++) {
            __syncthreads();                       // prior readers done (halo + A bufs)
            load_bhalo(sb, tid, pass, b, h, w0);   // commit
            load_agroup(sb, tid, 0, pass);         // commit

#pragma unroll 1
            for (int g = 0; g < 9; g++) {
                CP_WAIT(0);            // group g (and bhalo at g=0) resident
                __syncthreads();       // all warps done with overwritten buffer set
                if (g < 8) load_agroup(sb, tid, g + 1, pass);  // hidden under compute

#pragma unroll
                for (int i = 0; i < 3; i++) {
                    int t = g * 3 + i;
                    int kh = t / 9, r9 = t - kh * 9;
                    int kw = r9 / 3, kd = r9 - kw * 3;
                    uint32_t tapoff = (uint32_t)(kh * 204 + kw * 34 + kd);

                    uint32_t Ab = sb + A_OFF + ((g & 1) * 3 + i) * A_BYTES;
                    uint32_t sbb[2];
#pragma unroll
                    for (int nj2 = 0; nj2 < 2; nj2++)
                        sbb[nj2] = sb + rowaddr(brow[nj2] + tapoff, bcol);

#pragma unroll
                    for (int kq = 0; kq < 4; kq++) {
                        uint32_t kx = (uint32_t)(((kq + phase) & 3) * 32);
                        uint32_t a[2][4];
#pragma unroll
                        for (int mi = 0; mi < 2; mi++)
                            ldsm4(a[mi][0], a[mi][1], a[mi][2], a[mi][3], Ab + (sa[mi] ^ kx));
                        uint32_t bf[4][2];
#pragma unroll
                        for (int nj2 = 0; nj2 < 2; nj2++)
                            ldsm4(bf[2 * nj2][0], bf[2 * nj2][1], bf[2 * nj2 + 1][0],
                                  bf[2 * nj2 + 1][1], sbb[nj2] ^ kx);
#pragma unroll
                        for (int mi = 0; mi < 2; mi++)
#pragma unroll
                            for (int nj = 0; nj < 4; nj++)
                                mma16816(acc[mi][nj], a[mi], bf[nj]);
                    }
                }
            }
        }

        // ---- epilogue: demod scale + float2 stores (exclusive region) ----
#pragma unroll
        for (int mi = 0; mi < 2; mi++) {
#pragma unroll
            for (int rr = 0; rr < 2; rr++) {
                int oc = warp_m + mi * 16 + (lid >> 2) + rr * 8;
                float dm = g_demod[b * OCC + oc];
                float* obase = out + ((size_t)(b * OCC + oc) * SS + h) * 1024;
#pragma unroll
                for (int nj = 0; nj < 4; nj++) {
                    int n = warp_n + nj * 8 + 2 * (lid & 3);
                    int wl_ = n >> 5, d = n & 31;
                    float2 v;
                    v.x = acc[mi][nj][2 * rr + 0] * dm;
                    v.y = acc[mi][nj][2 * rr + 1] * dm;
                    *reinterpret_cast<float2*>(obase + (w0 + wl_) * 32 + d) = v;
                }
            }
        }

        // ---- next item (dynamic) ----
        __syncthreads();
        if (tid == 0) *next_item = atomicAdd(&g_ctr, 1u);
        __syncthreads();
        item = *next_item;
    }
}

// ---------------------------------------------------------------------------
extern "C" void kernel_launch(void* const* d_in, const int* in_sizes, int n_in,
                              void* d_out, int out_size) {
    const float* x = (const float*)d_in[0];
    const float* y = (const float*)d_in[1];
    const float* w = (const float*)d_in[2];
    float* out = (float*)d_out;

    cudaFuncSetAttribute(conv_kernel, cudaFuncAttributeMaxDynamicSharedMemorySize,
                         SMEM_TOTAL);

    demod_kernel<<<OCC, CC>>>(y, w);
    wconv_kernel<<<OCC, CC>>>(w);
    xconv_kernel<<<dim3(SS, SS, BB), 256>>>(x, y);
    conv_kernel<<<GRID, NTHR, SMEM_TOTAL>>>(out);
}

// round 15
// speedup vs baseline: 1.1053x; 1.0771x over previous
#include <cuda_runtime.h>
#include <cuda_fp16.h>
#include <cstdint>
#include <cstddef>

#define BB   4
#define CC   128
#define SS   32
#define OCC  128
#define EPSF 1e-8f

#define NTAP   27
#define BH_ROWS 612                  // 3 planes x 6 w x 34 dd
#define BH_BYTES (BH_ROWS * 128)     // 78336
#define A_BYTES 16384                // 128 oc x 128B (64 ic fp16)
#define NBUF_A 2
#define A_OFF  BH_BYTES
#define CTRL_OFF (A_OFF + NBUF_A * A_BYTES)   // 111104
#define SMEM_TOTAL (CTRL_OFF + 16)            // 111120 (x2 CTAs = 222240 <= 232448)
#define NTHR 256
#define NITEM 1024                   // 4 b x 32 h x 8 w-quads
#define GRID 296                     // 2 persistent CTAs per SM

__device__ float g_demod[BB * OCC];
__device__ unsigned g_ctr;
__device__ __align__(256) __half g_w16[NTAP * 2 * 128 * 64];
__device__ __align__(256) __half g_x16[(size_t)BB * SS * SS * SS * CC];

// ---------------- PTX helpers ----------------
__device__ __forceinline__ uint32_t smem_u32(const void* p) {
    uint32_t a;
    asm("{ .reg .u64 t; cvta.to.shared.u64 t, %1; cvt.u32.u64 %0, t; }" : "=r"(a) : "l"(p));
    return a;
}
__device__ __forceinline__ void cpasync16(uint32_t dst, const void* src, int sz) {
    asm volatile("cp.async.cg.shared.global [%0], [%1], 16, %2;"
                 :: "r"(dst), "l"(src), "r"(sz) : "memory");
}
#define CP_COMMIT() asm volatile("cp.async.commit_group;" ::: "memory")
#define CP_WAIT(n)  asm volatile("cp.async.wait_group %0;" :: "n"(n) : "memory")

__device__ __forceinline__ void ldsm4(uint32_t& r0, uint32_t& r1, uint32_t& r2,
                                      uint32_t& r3, uint32_t addr) {
    asm volatile("ldmatrix.sync.aligned.m8n8.x4.shared.b16 {%0,%1,%2,%3}, [%4];"
                 : "=r"(r0), "=r"(r1), "=r"(r2), "=r"(r3) : "r"(addr));
}
__device__ __forceinline__ void mma16816(float* c, const uint32_t* a, const uint32_t* b) {
    asm volatile(
        "mma.sync.aligned.m16n8k16.row.col.f32.f16.f16.f32 "
        "{%0,%1,%2,%3}, {%4,%5,%6,%7}, {%8,%9}, {%0,%1,%2,%3};"
        : "+f"(c[0]), "+f"(c[1]), "+f"(c[2]), "+f"(c[3])
        : "r"(a[0]), "r"(a[1]), "r"(a[2]), "r"(a[3]), "r"(b[0]), "r"(b[1]));
}
// swizzled addr of (row, colByte) in a 128B-row tile
__device__ __forceinline__ uint32_t rowaddr(uint32_t row, uint32_t colb) {
    return (row << 7) + (colb ^ ((row & 7) << 4));
}

// ---------------- prepass: demod (+ counter reset) ----------------
__global__ void demod_kernel(const float* __restrict__ y, const float* __restrict__ w) {
    int oc = blockIdx.x, ic = threadIdx.x;
    if (oc == 0 && ic == 0) g_ctr = GRID;
    const float* wp = w + (oc * CC + ic) * 27;
    float wsum = 0.f;
#pragma unroll
    for (int t = 0; t < 27; t++) { float v = wp[t]; wsum += v * v; }
    __shared__ float red[CC];
    for (int b = 0; b < BB; b++) {
        float yv = y[b * CC + ic];
        red[ic] = wsum * yv * yv;
        __syncthreads();
        for (int s = CC / 2; s > 0; s >>= 1) {
            if (ic < s) red[ic] += red[ic + s];
            __syncthreads();
        }
        if (ic == 0) g_demod[b * OCC + oc] = rsqrtf(red[0] + EPSF);
        __syncthreads();
    }
}

// ---------------- prepass: weight fp16, layout [tap*2+ichalf][oc][icl] ----------------
__global__ void wconv_kernel(const float* __restrict__ w) {
    int oc = blockIdx.x, ic = threadIdx.x;
    int ichalf = ic >> 6, icl = ic & 63;
#pragma unroll 1
    for (int t = 0; t < 27; t++) {
        float v = w[(oc * CC + ic) * 27 + t];
        int st = t * 2 + ichalf;
        g_w16[(st * 128 + oc) * 64 + icl] = __float2half(v);
    }
}

// ---------------- prepass: x transpose + y fold -> fp16; [b,h,w,d][ic] ----------------
__global__ __launch_bounds__(256) void xconv_kernel(const float* __restrict__ x,
                                                    const float* __restrict__ y) {
    __shared__ float ts[128][33];
    int w_ = blockIdx.x, h = blockIdx.y, b = blockIdx.z;
    int tid = threadIdx.x;
#pragma unroll
    for (int k = 0; k < 16; k++) {
        int e = tid + k * 256;
        int ic = e >> 5, d = e & 31;
        ts[ic][d] = x[((size_t)(b * CC + ic) * SS + h) * 1024 + w_ * SS + d] * y[b * CC + ic];
    }
    __syncthreads();
    size_t nb = (((size_t)(b * SS + h) * SS + w_) * SS) * CC;
#pragma unroll
    for (int k = 0; k < 16; k++) {
        int e = tid + k * 256;
        int d = e >> 7, ic = e & 127;
        g_x16[nb + (size_t)d * CC + ic] = __float2half(ts[ic][d]);
    }
}

// ---------------- B halo loader: 612 rows, zero-filled halo ----------------
__device__ __forceinline__ void load_bhalo(uint32_t sb, int tid, int pass,
                                           int b, int h, int w0) {
#pragma unroll 1
    for (int k = 0; k < 20; k++) {
        int i = tid + k * NTHR;
        if (i < BH_ROWS * 8) {
            int r = i >> 3, c = i & 7;
            int plane = r / 204;
            int rem   = r - plane * 204;
            int lw    = rem / 34;
            int dd    = rem - lw * 34;
            int gh = h + plane - 1, gw = w0 + lw - 1, gd = dd - 1;
            bool ok = (unsigned)gh < 32u && (unsigned)gw < 32u && (unsigned)gd < 32u;
            size_t n = ok ? (((size_t)(b * SS + gh) * SS + gw) * SS + gd) : 0;
            const char* src = (const char*)g_x16 + (n * CC + pass * 64) * 2 + c * 16;
            cpasync16(sb + rowaddr((uint32_t)r, c * 16), src, ok ? 16 : 0);
        }
    }
    CP_COMMIT();
}

// ---------------- A loader: one (tap,pass) slice into buf ----------------
__device__ __forceinline__ void load_a(uint32_t sb, int tid, int tap, int pass, int buf) {
    const char* ws = (const char*)(g_w16 + (size_t)(tap * 2 + pass) * 128 * 64);
    uint32_t base = sb + A_OFF + buf * A_BYTES;
#pragma unroll
    for (int k = 0; k < 4; k++) {
        int idx = tid + k * NTHR;
        int row = idx >> 3, c = idx & 7;
        cpasync16(base + rowaddr((uint32_t)row, c * 16),
                  ws + (size_t)row * 128 + c * 16, 16);
    }
    CP_COMMIT();
}

// ---------------- main conv: persistent implicit GEMM, 2 CTAs/SM ----------------
__global__ __launch_bounds__(NTHR, 2) void conv_kernel(float* __restrict__ out) {
    extern __shared__ char smem[];
    uint32_t sb = smem_u32(smem);
    unsigned* next_item = (unsigned*)(smem + CTRL_OFF);
    int tid = threadIdx.x;
    int wid = tid >> 5, lid = tid & 31;
    int phase = (wid >> 2) * 2;         // stagger kk across SMSP co-residents

    // warp grid: 4m x 2n ; warp tile 32(M) x 64(N)
    int warp_m = (wid & 3) * 32;
    int warp_n = (wid >> 2) * 64;

    // A: per-lane swizzled base offsets (within a 16KB A buffer)
    uint32_t sa[2];
#pragma unroll
    for (int mi = 0; mi < 2; mi++)
        sa[mi] = rowaddr((uint32_t)(warp_m + mi * 16 + (lid & 15)), (lid >> 4) * 16);

    // B: per-lane halo row base (n -> lw*34 + d) and col byte
    uint32_t brow[4];
    uint32_t bcol = ((lid >> 3) & 1) * 16;
#pragma unroll
    for (int nj2 = 0; nj2 < 4; nj2++) {
        int n = warp_n + nj2 * 16 + (lid & 7) + ((lid >> 4) & 1) * 8;
        brow[nj2] = (uint32_t)((n >> 5) * 34 + (n & 31));
    }

    unsigned item = blockIdx.x;
    while (item < NITEM) {
        int b  = item >> 8;
        int h  = (item >> 3) & 31;
        int w0 = (item & 7) * 4;

        float acc[2][8][4];
#pragma unroll
        for (int mi = 0; mi < 2; mi++)
#pragma unroll
            for (int nj = 0; nj < 8; nj++)
#pragma unroll
                for (int q = 0; q < 4; q++) acc[mi][nj][q] = 0.f;

#pragma unroll 1
        for (int pass = 0; pass < 2; pass++) {
            __syncthreads();                       // prior readers done (halo + A bufs)
            load_bhalo(sb, tid, pass, b, h, w0);   // commit
            load_a(sb, tid, 0, pass, 0);           // commit

#pragma unroll 1
            for (int t = 0; t < NTAP; t++) {
                CP_WAIT(0);            // tap t A (and halo at t=0) resident
                __syncthreads();       // all warps done reading buf (t-1)&1
                if (t + 1 < NTAP) load_a(sb, tid, t + 1, pass, (t + 1) & 1);

                int kh = t / 9, r9 = t - kh * 9;
                int kw = r9 / 3, kd = r9 - kw * 3;
                uint32_t tapoff = (uint32_t)(kh * 204 + kw * 34 + kd);

                uint32_t Ab = sb + A_OFF + (t & 1) * A_BYTES;
                uint32_t sbb[4];
#pragma unroll
                for (int nj2 = 0; nj2 < 4; nj2++)
                    sbb[nj2] = sb + rowaddr(brow[nj2] + tapoff, bcol);

#pragma unroll
                for (int kq = 0; kq < 4; kq++) {
                    uint32_t kx = (uint32_t)(((kq + phase) & 3) * 32);
                    uint32_t a[2][4];
#pragma unroll
                    for (int mi = 0; mi < 2; mi++)
                        ldsm4(a[mi][0], a[mi][1], a[mi][2], a[mi][3], Ab + (sa[mi] ^ kx));
                    uint32_t bf[8][2];
#pragma unroll
                    for (int nj2 = 0; nj2 < 4; nj2++)
                        ldsm4(bf[2 * nj2][0], bf[2 * nj2][1], bf[2 * nj2 + 1][0],
                              bf[2 * nj2 + 1][1], sbb[nj2] ^ kx);
#pragma unroll
                    for (int mi = 0; mi < 2; mi++)
#pragma unroll
                        for (int nj = 0; nj < 8; nj++)
                            mma16816(acc[mi][nj], a[mi], bf[nj]);
                }
            }
        }

        // ---- epilogue: demod scale + float2 stores (exclusive region) ----
#pragma unroll
        for (int mi = 0; mi < 2; mi++) {
#pragma unroll
            for (int rr = 0; rr < 2; rr++) {
                int oc = warp_m + mi * 16 + (lid >> 2) + rr * 8;
                float dm = g_demod[b * OCC + oc];
                float* obase = out + ((size_t)(b * OCC + oc) * SS + h) * 1024;
#pragma unroll
                for (int nj = 0; nj < 8; nj++) {
                    int n = warp_n + nj * 8 + 2 * (lid & 3);
                    int wl_ = n >> 5, d = n & 31;
                    float2 v;
                    v.x = acc[mi][nj][2 * rr + 0] * dm;
                    v.y = acc[mi][nj][2 * rr + 1] * dm;
                    *reinterpret_cast<float2*>(obase + (w0 + wl_) * 32 + d) = v;
                }
            }
        }

        // ---- next item (dynamic) ----
        __syncthreads();
        if (tid == 0) *next_item = atomicAdd(&g_ctr, 1u);
        __syncthreads();
        item = *next_item;
    }
}

// ---------------------------------------------------------------------------
extern "C" void kernel_launch(void* const* d_in, const int* in_sizes, int n_in,
                              void* d_out, int out_size) {
    const float* x = (const float*)d_in[0];
    const float* y = (const float*)d_in[1];
    const float* w = (const float*)d_in[2];
    float* out = (float*)d_out;

    cudaFuncSetAttribute(conv_kernel, cudaFuncAttributeMaxDynamicSharedMemorySize,
                         SMEM_TOTAL);

    demod_kernel<<<OCC, CC>>>(y, w);
    wconv_kernel<<<OCC, CC>>>(w);
    xconv_kernel<<<dim3(SS, SS, BB), 256>>>(x, y);
    conv_kernel<<<GRID, NTHR, SMEM_TOTAL>>>(out);
}